// round 3
// baseline (speedup 1.0000x reference)
#include <cuda_runtime.h>
#include <math.h>

// ---------------------------------------------------------------------------
// Scratch: node state (normalized x) and aggregation buffer. N = 1,000,000
// fits in 1<<20. Static __device__ arrays (no allocation anywhere).
// ---------------------------------------------------------------------------
#define MAXN (1 << 20)
__device__ float2 g_xn[MAXN];
__device__ float2 g_agg[MAXN];
__device__ int    g_idx64;   // 1 if edge_index delivered as int64, 0 if int32

#define EPSF 1e-15f

// Vectorized fire-and-forget float2 reduction into global memory (sm_90+).
__device__ __forceinline__ void red_add_f32x2(float2* p, float vx, float vy) {
    asm volatile("red.global.add.v2.f32 [%0], {%1, %2};"
                 :: "l"(p), "f"(vx), "f"(vy)
                 : "memory");
}

// ---------------------------------------------------------------------------
// Kernel 0: dtype detection. Interpret the first up-to-2048 8-byte words as
// int64; if ANY is outside [0, N) the buffer is int32 (two packed indices per
// word make a huge int64 with probability ~1 for random indices < N).
// Single block; deterministic.
// ---------------------------------------------------------------------------
__global__ void k_detect(const long long* __restrict__ ei, long long n_words, int N) {
    __shared__ int bad;
    if (threadIdx.x == 0) bad = 0;
    __syncthreads();
    long long lim = n_words < 2048 ? n_words : 2048;
    int local_bad = 0;
    for (long long i = threadIdx.x; i < lim; i += blockDim.x) {
        long long v = ei[i];
        if (v < 0 || v >= (long long)N) local_bad = 1;
    }
    if (local_bad) bad = 1;
    __syncthreads();
    if (threadIdx.x == 0) g_idx64 = bad ? 0 : 1;
}

// ---------------------------------------------------------------------------
// Kernel 1: normalize input x into g_xn, zero g_agg.
// ---------------------------------------------------------------------------
__global__ void k_init(const float2* __restrict__ x, int N) {
    int i = blockIdx.x * blockDim.x + threadIdx.x;
    if (i >= N) return;
    float2 v = x[i];
    float n = sqrtf(v.x * v.x + v.y * v.y) + EPSF;
    float inv = 1.0f / n;
    g_xn[i] = make_float2(v.x * inv, v.y * inv);
    g_agg[i] = make_float2(0.0f, 0.0f);
}

// ---------------------------------------------------------------------------
// Kernel 2: edge scatter. g_agg[dst[e]] += g_xn[src[e]] for all edges.
// Uniform branch on detected index dtype.
//   int32 path: 4 edges per iter via int4 loads (fully coalesced, MLP=8).
//   int64 path: 2 edges per iter via longlong2 loads.
// Node arrays (8 MB each) are L2-resident; the index stream is HBM-bound.
// ---------------------------------------------------------------------------
__global__ void k_scatter(const void* __restrict__ eiv, long long E) {
    long long tid    = (long long)blockIdx.x * blockDim.x + threadIdx.x;
    long long stride = (long long)gridDim.x * blockDim.x;

    if (g_idx64 == 0) {
        const int* src = (const int*)eiv;
        const int* dst = src + E;
        long long quads = E >> 2;
        for (long long q = tid; q < quads; q += stride) {
            int4 s = __ldg((const int4*)(src + 4 * q));
            int4 d = __ldg((const int4*)(dst + 4 * q));
            float2 v0 = g_xn[s.x];
            float2 v1 = g_xn[s.y];
            float2 v2 = g_xn[s.z];
            float2 v3 = g_xn[s.w];
            red_add_f32x2(&g_agg[d.x], v0.x, v0.y);
            red_add_f32x2(&g_agg[d.y], v1.x, v1.y);
            red_add_f32x2(&g_agg[d.z], v2.x, v2.y);
            red_add_f32x2(&g_agg[d.w], v3.x, v3.y);
        }
        if (tid == 0) {
            for (long long e = quads * 4; e < E; e++) {
                float2 v = g_xn[src[e]];
                red_add_f32x2(&g_agg[dst[e]], v.x, v.y);
            }
        }
    } else {
        const long long* src = (const long long*)eiv;
        const long long* dst = src + E;
        long long pairs = E >> 1;
        for (long long p = tid; p < pairs; p += stride) {
            longlong2 s = __ldg((const longlong2*)(src + 2 * p));
            longlong2 d = __ldg((const longlong2*)(dst + 2 * p));
            float2 v0 = g_xn[(int)s.x];
            float2 v1 = g_xn[(int)s.y];
            red_add_f32x2(&g_agg[(int)d.x], v0.x, v0.y);
            red_add_f32x2(&g_agg[(int)d.y], v1.x, v1.y);
        }
        if (tid == 0 && (E & 1LL)) {
            long long e = E - 1;
            float2 v = g_xn[(int)src[e]];
            red_add_f32x2(&g_agg[(int)dst[e]], v.x, v.y);
        }
    }
}

// ---------------------------------------------------------------------------
// Kernel 3: mid-iteration: y = relu(agg @ W); renormalize into g_xn;
// zero g_agg for the next scatter pass. W row-major 2x2.
// ---------------------------------------------------------------------------
__global__ void k_mid(const float* __restrict__ W, int N) {
    int i = blockIdx.x * blockDim.x + threadIdx.x;
    if (i >= N) return;
    float w00 = W[0], w01 = W[1], w10 = W[2], w11 = W[3];
    float2 a = g_agg[i];
    float y0 = fmaxf(fmaf(a.y, w10, a.x * w00), 0.0f);
    float y1 = fmaxf(fmaf(a.y, w11, a.x * w01), 0.0f);
    float n = sqrtf(y0 * y0 + y1 * y1) + EPSF;
    float inv = 1.0f / n;
    g_xn[i] = make_float2(y0 * inv, y1 * inv);
    g_agg[i] = make_float2(0.0f, 0.0f);
}

// ---------------------------------------------------------------------------
// Kernel 4: final: y = relu(agg @ W); out = sigmoid(y . final_weight).
// ---------------------------------------------------------------------------
__global__ void k_final(const float* __restrict__ W,
                        const float* __restrict__ fw,
                        float* __restrict__ out, int N) {
    int i = blockIdx.x * blockDim.x + threadIdx.x;
    if (i >= N) return;
    float w00 = W[0], w01 = W[1], w10 = W[2], w11 = W[3];
    float f0 = fw[0], f1 = fw[1];
    float2 a = g_agg[i];
    float y0 = fmaxf(fmaf(a.y, w10, a.x * w00), 0.0f);
    float y1 = fmaxf(fmaf(a.y, w11, a.x * w01), 0.0f);
    float s = fmaf(y1, f1, y0 * f0);
    out[i] = 1.0f / (1.0f + expf(-s));
}

// ---------------------------------------------------------------------------
// Launch: detect -> init -> scatter -> mid -> scatter -> final.
// Default stream, graph-capturable, allocation-free, no syncs.
// ---------------------------------------------------------------------------
extern "C" void kernel_launch(void* const* d_in, const int* in_sizes, int n_in,
                              void* d_out, int out_size) {
    const float* x  = (const float*)d_in[0];
    const void*  ei = (const void*)d_in[1];
    const float* W  = (const float*)d_in[2];
    const float* fw = (const float*)d_in[3];
    float* out = (float*)d_out;

    int N = in_sizes[0] / 2;
    long long E = (long long)in_sizes[1] / 2;   // elements = 2*E regardless of dtype

    const int TB = 256;
    int nb = (N + TB - 1) / TB;
    const int SCATTER_BLOCKS = 8192;

    // n_words for detection: if int64, buffer has 2E 8-byte words; if int32 it
    // has E 8-byte words. Use E (the smaller) as the safe bound.
    k_detect<<<1, 256>>>((const long long*)ei, E, N);
    k_init<<<nb, TB>>>((const float2*)x, N);
    k_scatter<<<SCATTER_BLOCKS, TB>>>(ei, E);
    k_mid<<<nb, TB>>>(W, N);
    k_scatter<<<SCATTER_BLOCKS, TB>>>(ei, E);
    k_final<<<nb, TB>>>(W, fw, out, N);

    (void)n_in; (void)out_size;
}